// round 1
// baseline (speedup 1.0000x reference)
#include <cuda_runtime.h>
#include <cuda_bf16.h>
#include <cstdint>

// Problem constants
#define BATCH 2048
#define SEQ   64
#define EDIM  512
#define UDIM  512
#define HDIM  512

// Scratch for h2e = hidden@W2 + b1 + b2   [2048 x 512]
__device__ float g_h2e[BATCH * UDIM];

// ---------------------------------------------------------------------------
// helpers
// ---------------------------------------------------------------------------
__device__ __forceinline__ float tf32r(float x) {
    uint32_t u;
    asm("cvt.rna.tf32.f32 %0, %1;" : "=r"(u) : "f"(x));
    return __uint_as_float(u);
}

__device__ __forceinline__ void mma_tf32(float c[4], const float a[4], const float b[2]) {
    asm volatile(
        "mma.sync.aligned.m16n8k8.row.col.f32.tf32.tf32.f32 "
        "{%0,%1,%2,%3}, {%4,%5,%6,%7}, {%8,%9}, {%0,%1,%2,%3};\n"
        : "+f"(c[0]), "+f"(c[1]), "+f"(c[2]), "+f"(c[3])
        : "r"(__float_as_uint(a[0])), "r"(__float_as_uint(a[1])),
          "r"(__float_as_uint(a[2])), "r"(__float_as_uint(a[3])),
          "r"(__float_as_uint(b[0])), "r"(__float_as_uint(b[1])));
}

// ---------------------------------------------------------------------------
// Kernel 1: h2e[b,u] = sum_h hidden[b,h] * W2[h,u] + b1[u] + b2[u]
// Classic SIMT fp32 tiled GEMM, BM=BN=64, BK=16, 256 threads, 4x4 microtile.
// ---------------------------------------------------------------------------
__global__ __launch_bounds__(256) void h2_kernel(
    const float* __restrict__ hidden,
    const float* __restrict__ W2,
    const float* __restrict__ b1,
    const float* __restrict__ b2,
    float* __restrict__ h2e)
{
    __shared__ float As[16][68];  // [k][m]
    __shared__ float Bs[16][68];  // [k][n]

    const int tid  = threadIdx.x;
    const int tx   = tid & 15;        // 0..15 -> col groups
    const int ty   = tid >> 4;        // 0..15 -> row groups
    const int row0 = blockIdx.y * 64;
    const int col0 = blockIdx.x * 64;

    float c[4][4];
#pragma unroll
    for (int i = 0; i < 4; i++)
#pragma unroll
        for (int j = 0; j < 4; j++) c[i][j] = 0.f;

    for (int kb = 0; kb < HDIM / 16; kb++) {
        const int kbase = kb * 16;
        // load A tile (64 x 16): k = tid&15, m = (tid>>4) + 16*p
        {
            const int k = tid & 15;
            const int m = tid >> 4;
#pragma unroll
            for (int p = 0; p < 4; p++) {
                As[k][m + 16 * p] = hidden[(size_t)(row0 + m + 16 * p) * HDIM + kbase + k];
            }
        }
        // load B tile (16 x 64): k = (tid>>6) + 4*p, n = tid&63
        {
            const int k = tid >> 6;
            const int n = tid & 63;
#pragma unroll
            for (int p = 0; p < 4; p++) {
                Bs[k + 4 * p][n] = W2[(size_t)(kbase + k + 4 * p) * UDIM + col0 + n];
            }
        }
        __syncthreads();

#pragma unroll
        for (int k = 0; k < 16; k++) {
            float ra[4], rb[4];
#pragma unroll
            for (int i = 0; i < 4; i++) ra[i] = As[k][ty * 4 + i];
#pragma unroll
            for (int j = 0; j < 4; j++) rb[j] = Bs[k][tx * 4 + j];
#pragma unroll
            for (int i = 0; i < 4; i++)
#pragma unroll
                for (int j = 0; j < 4; j++) c[i][j] += ra[i] * rb[j];
        }
        __syncthreads();
    }

#pragma unroll
    for (int i = 0; i < 4; i++) {
        const int r = row0 + ty * 4 + i;
#pragma unroll
        for (int j = 0; j < 4; j++) {
            const int u = col0 + tx * 4 + j;
            h2e[(size_t)r * UDIM + u] = c[i][j] + b1[u] + b2[u];
        }
    }
}

// ---------------------------------------------------------------------------
// Kernel 2: fused per-batch attention
//   h1 = features[b] @ W1  (tf32 mma.sync), + h2e, tanh, dot Wv -> scores[64]
//   softmax over seq, context[b,:] = sum_s w_s * features[b,s,:]
//
// One CTA per batch. 256 threads = 8 warps (2x4 warp grid, warp tile 32x32).
// features[b] resident in smem (tf32-rounded, stride 516 -> conflict-free).
// W1 streamed in 16x128 tiles (stride 136 -> conflict-free), double buffered.
// ---------------------------------------------------------------------------
#define FSTRIDE 516
#define WSTRIDE 136
#define WTILE   (16 * WSTRIDE)   // floats per W1 buffer

// smem layout (floats):
//   feat   : 64*516            = 33024
//   w1s    : 2*16*136          =  4352
//   scores : 64
//   wts    : 64
//   h2s    : 512
//   wvs    : 512
#define SMEM_FLOATS (64 * FSTRIDE + 2 * WTILE + 64 + 64 + 512 + 512)

__global__ __launch_bounds__(256) void attn_kernel(
    const float* __restrict__ features,
    const float* __restrict__ W1,
    const float* __restrict__ Wv,
    const float* __restrict__ h2e,
    float* __restrict__ out)
{
    extern __shared__ float smem[];
    float* feat   = smem;
    float* w1s    = smem + 64 * FSTRIDE;
    float* scores = w1s + 2 * WTILE;
    float* wts    = scores + 64;
    float* h2s    = wts + 64;
    float* wvs    = h2s + 512;

    const int b    = blockIdx.x;
    const int tid  = threadIdx.x;
    const int lane = tid & 31;
    const int wid  = tid >> 5;
    const int wm   = wid >> 2;     // 0..1  (row 32-blocks)
    const int wn   = wid & 3;      // 0..3  (col 32-blocks within 128-chunk)
    const int l4   = lane >> 2;    // 0..7
    const int lm4  = lane & 3;     // 0..3

    // ---- load features[b] (64x512) into smem, tf32-rounded ----
    {
        const float4* src = (const float4*)(features + (size_t)b * SEQ * EDIM);
#pragma unroll
        for (int j = 0; j < 32; j++) {
            const int idx = tid + 256 * j;      // float4 index, 8192 total
            float4 v = src[idx];
            const int lin = idx * 4;
            const int r = lin >> 9;             // /512
            const int cc = lin & 511;
            float* d = feat + r * FSTRIDE + cc;
            d[0] = tf32r(v.x); d[1] = tf32r(v.y); d[2] = tf32r(v.z); d[3] = tf32r(v.w);
        }
    }
    // ---- h2e row + Wv into smem; init scores ----
    {
        const float* h2row = h2e + (size_t)b * UDIM;
        h2s[tid]       = h2row[tid];
        h2s[tid + 256] = h2row[tid + 256];
        wvs[tid]       = Wv[tid];
        wvs[tid + 256] = Wv[tid + 256];
        if (tid < 64) scores[tid] = 0.f;
    }
    __syncthreads();

    float partial[4] = {0.f, 0.f, 0.f, 0.f};   // score partials for 4 rows
    const int r0 = wm * 32 + l4;

    // global-load / smem-store helpers for W1 tiles
    const int w_rr = tid >> 5;           // 0..7 (k row within tile, +8 for second)
    const int w_c4 = (tid & 31) << 2;    // col within 128-chunk

    for (int uc = 0; uc < 4; uc++) {
        const int u0 = uc * 128;

        float acc[2][4][4];
#pragma unroll
        for (int mf = 0; mf < 2; mf++)
#pragma unroll
            for (int nf = 0; nf < 4; nf++)
#pragma unroll
                for (int q = 0; q < 4; q++) acc[mf][nf][q] = 0.f;

        // prefetch tile 0
        float4 pre0, pre1;
        pre0 = *(const float4*)(W1 + (size_t)(0 * 16 + w_rr) * UDIM + u0 + w_c4);
        pre1 = *(const float4*)(W1 + (size_t)(0 * 16 + w_rr + 8) * UDIM + u0 + w_c4);
        {
            float* d0 = w1s + w_rr * WSTRIDE + w_c4;
            float* d1 = w1s + (w_rr + 8) * WSTRIDE + w_c4;
            d0[0] = tf32r(pre0.x); d0[1] = tf32r(pre0.y); d0[2] = tf32r(pre0.z); d0[3] = tf32r(pre0.w);
            d1[0] = tf32r(pre1.x); d1[1] = tf32r(pre1.y); d1[2] = tf32r(pre1.z); d1[3] = tf32r(pre1.w);
        }
        __syncthreads();

        for (int kt = 0; kt < 32; kt++) {
            if (kt + 1 < 32) {
                pre0 = *(const float4*)(W1 + (size_t)((kt + 1) * 16 + w_rr) * UDIM + u0 + w_c4);
                pre1 = *(const float4*)(W1 + (size_t)((kt + 1) * 16 + w_rr + 8) * UDIM + u0 + w_c4);
            }
            const float* buf = w1s + (kt & 1) * WTILE;
            const int kbase = kt * 16;

#pragma unroll
            for (int ks = 0; ks < 2; ks++) {
                const int kk = ks * 8;
                // A fragments (from resident features)
                float a[2][4];
                const float* fb = feat + kbase + kk + lm4;
#pragma unroll
                for (int mf = 0; mf < 2; mf++) {
                    const int rr = r0 + mf * 16;
                    a[mf][0] = fb[(rr)     * FSTRIDE];
                    a[mf][1] = fb[(rr + 8) * FSTRIDE];
                    a[mf][2] = fb[(rr)     * FSTRIDE + 4];
                    a[mf][3] = fb[(rr + 8) * FSTRIDE + 4];
                }
                // B fragments
                float bf[4][2];
#pragma unroll
                for (int nf = 0; nf < 4; nf++) {
                    const int col = wn * 32 + nf * 8 + l4;
                    bf[nf][0] = buf[(kk + lm4)     * WSTRIDE + col];
                    bf[nf][1] = buf[(kk + lm4 + 4) * WSTRIDE + col];
                }
#pragma unroll
                for (int mf = 0; mf < 2; mf++)
#pragma unroll
                    for (int nf = 0; nf < 4; nf++)
                        mma_tf32(acc[mf][nf], a[mf], bf[nf]);
            }

            if (kt + 1 < 32) {
                float* d0 = w1s + ((kt + 1) & 1) * WTILE + w_rr * WSTRIDE + w_c4;
                float* d1 = w1s + ((kt + 1) & 1) * WTILE + (w_rr + 8) * WSTRIDE + w_c4;
                d0[0] = tf32r(pre0.x); d0[1] = tf32r(pre0.y); d0[2] = tf32r(pre0.z); d0[3] = tf32r(pre0.w);
                d1[0] = tf32r(pre1.x); d1[1] = tf32r(pre1.y); d1[2] = tf32r(pre1.z); d1[3] = tf32r(pre1.w);
            }
            __syncthreads();
        }

        // fused epilogue for this 128-col chunk: +h2e, tanh, dot Wv
#pragma unroll
        for (int mf = 0; mf < 2; mf++) {
#pragma unroll
            for (int nf = 0; nf < 4; nf++) {
                const int u = u0 + wn * 32 + nf * 8 + 2 * lm4;
                const float h2a = h2s[u], h2b = h2s[u + 1];
                const float wa = wvs[u], wb = wvs[u + 1];
                partial[mf * 2 + 0] += tanhf(acc[mf][nf][0] + h2a) * wa
                                     + tanhf(acc[mf][nf][1] + h2b) * wb;
                partial[mf * 2 + 1] += tanhf(acc[mf][nf][2] + h2a) * wa
                                     + tanhf(acc[mf][nf][3] + h2b) * wb;
            }
        }
    }

    // ---- reduce score partials ----
    {
        const int rows[4] = {r0, r0 + 8, r0 + 16, r0 + 24};
#pragma unroll
        for (int p = 0; p < 4; p++) {
            float v = partial[p];
            v += __shfl_xor_sync(0xffffffffu, v, 1);
            v += __shfl_xor_sync(0xffffffffu, v, 2);
            if (lm4 == 0) atomicAdd(&scores[rows[p]], v);
        }
    }
    __syncthreads();

    // ---- softmax over 64 scores (warp 0) ----
    if (wid == 0) {
        float s0 = scores[lane];
        float s1 = scores[lane + 32];
        float m = fmaxf(s0, s1);
#pragma unroll
        for (int off = 16; off > 0; off >>= 1)
            m = fmaxf(m, __shfl_xor_sync(0xffffffffu, m, off));
        float e0 = __expf(s0 - m);
        float e1 = __expf(s1 - m);
        float sum = e0 + e1;
#pragma unroll
        for (int off = 16; off > 0; off >>= 1)
            sum += __shfl_xor_sync(0xffffffffu, sum, off);
        const float inv = 1.f / sum;
        wts[lane]      = e0 * inv;
        wts[lane + 32] = e1 * inv;
    }
    __syncthreads();

    // ---- context[b,:] = sum_s w_s * features[b,s,:] (from resident smem) ----
    {
        float2 acc2 = make_float2(0.f, 0.f);
        const int e = 2 * tid;   // 0..510
        for (int s = 0; s < 64; s++) {
            const float w = wts[s];
            const float2 f = *(const float2*)(feat + s * FSTRIDE + e);
            acc2.x += w * f.x;
            acc2.y += w * f.y;
        }
        *(float2*)(out + (size_t)b * EDIM + e) = acc2;
    }
}

// ---------------------------------------------------------------------------
// launch
// ---------------------------------------------------------------------------
extern "C" void kernel_launch(void* const* d_in, const int* in_sizes, int n_in,
                              void* d_out, int out_size)
{
    const float* features = (const float*)d_in[0];
    const float* hidden   = (const float*)d_in[1];
    const float* W1       = (const float*)d_in[2];
    const float* b1       = (const float*)d_in[3];
    const float* W2       = (const float*)d_in[4];
    const float* b2       = (const float*)d_in[5];
    const float* Wv       = (const float*)d_in[6];
    // d_in[7] = bv: softmax-invariant constant shift, intentionally unused.
    float* out = (float*)d_out;

    float* h2e;
    cudaGetSymbolAddress((void**)&h2e, g_h2e);

    // K1: h2e = hidden @ W2 + b1 + b2
    {
        dim3 grid(UDIM / 64, BATCH / 64);
        h2_kernel<<<grid, 256>>>(hidden, W2, b1, b2, h2e);
    }

    // K2: fused attention
    {
        static const size_t smem_bytes = SMEM_FLOATS * sizeof(float);
        cudaFuncSetAttribute(attn_kernel,
                             cudaFuncAttributeMaxDynamicSharedMemorySize,
                             (int)smem_bytes);
        attn_kernel<<<BATCH, 256, smem_bytes>>>(features, W1, Wv, h2e, out);
    }
}

// round 6
// speedup vs baseline: 1.8393x; 1.8393x over previous
#include <cuda_runtime.h>
#include <cuda_bf16.h>
#include <cstdint>

// Problem constants
#define BATCH 2048
#define SEQ   64
#define EDIM  512
#define UDIM  512
#define HDIM  512

// Scratch
__device__ float g_h2e[BATCH * UDIM];        // hidden@W2 + b1 + b2
__device__ float g_w1tf[EDIM * UDIM];        // W1 pre-rounded to tf32
__device__ float g_sp[BATCH * 4 * SEQ];      // partial scores per u-chunk

// ---------------------------------------------------------------------------
// helpers
// ---------------------------------------------------------------------------
__device__ __forceinline__ float tf32r(float x) {
    uint32_t u;
    asm("cvt.rna.tf32.f32 %0, %1;" : "=r"(u) : "f"(x));
    return __uint_as_float(u);
}

__device__ __forceinline__ void mma_tf32(float c[4], const float a[4], const float b[2]) {
    asm volatile(
        "mma.sync.aligned.m16n8k8.row.col.f32.tf32.tf32.f32 "
        "{%0,%1,%2,%3}, {%4,%5,%6,%7}, {%8,%9}, {%0,%1,%2,%3};\n"
        : "+f"(c[0]), "+f"(c[1]), "+f"(c[2]), "+f"(c[3])
        : "r"(__float_as_uint(a[0])), "r"(__float_as_uint(a[1])),
          "r"(__float_as_uint(a[2])), "r"(__float_as_uint(a[3])),
          "r"(__float_as_uint(b[0])), "r"(__float_as_uint(b[1])));
}

__device__ __forceinline__ void cpasync16(float* dst, const float* src) {
    uint32_t d = (uint32_t)__cvta_generic_to_shared(dst);
    asm volatile("cp.async.cg.shared.global [%0], [%1], 16;\n" :: "r"(d), "l"(src));
}
#define CP_COMMIT() asm volatile("cp.async.commit_group;\n" ::: "memory")
#define CP_WAIT1()  asm volatile("cp.async.wait_group 1;\n" ::: "memory")
#define CP_WAIT0()  asm volatile("cp.async.wait_group 0;\n" ::: "memory")

// ---------------------------------------------------------------------------
// Kernel 0: round W1 to tf32 once (removes cvt from GEMM inner loop for B)
// ---------------------------------------------------------------------------
__global__ __launch_bounds__(256) void convW1_kernel(
    const float* __restrict__ W1, float* __restrict__ w1tf)
{
    const int i = blockIdx.x * 256 + threadIdx.x;   // float4 index
    float4 v = ((const float4*)W1)[i];
    float4 o;
    o.x = tf32r(v.x); o.y = tf32r(v.y); o.z = tf32r(v.z); o.w = tf32r(v.w);
    ((float4*)w1tf)[i] = o;
}

// ---------------------------------------------------------------------------
// Kernel 1: h2e[b,u] = hidden@W2 + b1 + b2  (SIMT fp32, 64x64x16 tiles)
// ---------------------------------------------------------------------------
__global__ __launch_bounds__(256) void h2_kernel(
    const float* __restrict__ hidden,
    const float* __restrict__ W2,
    const float* __restrict__ b1,
    const float* __restrict__ b2,
    float* __restrict__ h2e)
{
    __shared__ float As[16][68];
    __shared__ float Bs[16][68];

    const int tid  = threadIdx.x;
    const int tx   = tid & 15;
    const int ty   = tid >> 4;
    const int row0 = blockIdx.y * 64;
    const int col0 = blockIdx.x * 64;

    float c[4][4];
#pragma unroll
    for (int i = 0; i < 4; i++)
#pragma unroll
        for (int j = 0; j < 4; j++) c[i][j] = 0.f;

    for (int kb = 0; kb < HDIM / 16; kb++) {
        const int kbase = kb * 16;
        {
            const int k = tid & 15;
            const int m = tid >> 4;
#pragma unroll
            for (int p = 0; p < 4; p++)
                As[k][m + 16 * p] = hidden[(size_t)(row0 + m + 16 * p) * HDIM + kbase + k];
        }
        {
            const int k = tid >> 6;
            const int n = tid & 63;
#pragma unroll
            for (int p = 0; p < 4; p++)
                Bs[k + 4 * p][n] = W2[(size_t)(kbase + k + 4 * p) * UDIM + col0 + n];
        }
        __syncthreads();
#pragma unroll
        for (int k = 0; k < 16; k++) {
            float ra[4], rb[4];
#pragma unroll
            for (int i = 0; i < 4; i++) ra[i] = As[k][ty * 4 + i];
#pragma unroll
            for (int j = 0; j < 4; j++) rb[j] = Bs[k][tx * 4 + j];
#pragma unroll
            for (int i = 0; i < 4; i++)
#pragma unroll
                for (int j = 0; j < 4; j++) c[i][j] += ra[i] * rb[j];
        }
        __syncthreads();
    }
#pragma unroll
    for (int i = 0; i < 4; i++) {
        const int r = row0 + ty * 4 + i;
#pragma unroll
        for (int j = 0; j < 4; j++) {
            const int u = col0 + tx * 4 + j;
            h2e[(size_t)r * UDIM + u] = c[i][j] + b1[u] + b2[u];
        }
    }
}

// ---------------------------------------------------------------------------
// Kernel A: scores_part[b][uc][s] = sum_{u in chunk uc} tanh(h1[b,s,u]+h2e[b,u])*Wv[u]
// CTA tile: M=128 (2 batches x 64 seq), N=128 (u-chunk), K=512.
// 256 threads = 8 warps (2 wm x 4 wn), warp tile 64x32, tf32 mma.sync.
// 3-stage cp.async pipeline, K-tile 32.
// Tail fix: final iteration uses wait_group 0 (newest committed group is the
// one being consumed at kt=15; wait_group 1 would race it).
// ---------------------------------------------------------------------------
#define NSTAGE 3
#define AST 36                 // A tile stride (floats): 128 rows x 32 k
#define BST 132                // B tile stride (floats): 32 k x 128 n
#define AFL (128 * AST)        // 4608
#define BFL (32 * BST)         // 4224
#define STAGEFL (AFL + BFL)    // 8832
#define SMEMA_FLOATS (NSTAGE * STAGEFL + 256 + 128 + 128)

__global__ __launch_bounds__(256, 2) void attnA_kernel(
    const float* __restrict__ features,
    const float* __restrict__ w1tf,
    const float* __restrict__ Wv,
    const float* __restrict__ h2e,
    float* __restrict__ scores_part)
{
    extern __shared__ float smem[];
    float* h2s = smem + NSTAGE * STAGEFL;   // [2][128]
    float* wvs = h2s + 256;                 // [128]
    float* scs = wvs + 128;                 // [128]

    const int uc  = blockIdx.x;
    const int b0  = blockIdx.y * 2;
    const int u0  = uc * 128;
    const int tid = threadIdx.x;
    const int lane = tid & 31, wid = tid >> 5;
    const int wm = wid >> 2, wn = wid & 3;
    const int l4 = lane >> 2, lm4 = lane & 3;

    const float* fbase = features + (size_t)b0 * SEQ * EDIM;

    // prologue small loads
    h2s[tid] = h2e[(size_t)(b0 + (tid >> 7)) * UDIM + u0 + (tid & 127)];
    if (tid < 128) { wvs[tid] = Wv[u0 + tid]; scs[tid] = 0.f; }

    auto issue = [&](int kt, int st) {
        float* As = smem + st * STAGEFL;
        float* Bs = As + AFL;
#pragma unroll
        for (int i = 0; i < 4; i++) {
            const int c = tid + 256 * i;
            const int row = c >> 3, kc = c & 7;
            cpasync16(As + row * AST + kc * 4,
                      fbase + (size_t)row * EDIM + kt * 32 + kc * 4);
        }
#pragma unroll
        for (int i = 0; i < 4; i++) {
            const int c = tid + 256 * i;
            const int row = c >> 5, c4 = (c & 31) << 2;
            cpasync16(Bs + row * BST + c4,
                      w1tf + (size_t)(kt * 32 + row) * UDIM + u0 + c4);
        }
        CP_COMMIT();
    };

    float acc[4][4][4];
#pragma unroll
    for (int mf = 0; mf < 4; mf++)
#pragma unroll
        for (int nf = 0; nf < 4; nf++)
#pragma unroll
            for (int q = 0; q < 4; q++) acc[mf][nf][q] = 0.f;

    issue(0, 0);
    issue(1, 1);

    for (int kt = 0; kt < 16; kt++) {
        // At kt<=14 the newest committed group is g_{kt+1} (or g15), and we
        // consume g_kt -> wait_group 1 suffices. At kt==15 the newest group
        // IS g15 = the stage we consume -> must drain fully.
        if (kt == 15) { CP_WAIT0(); } else { CP_WAIT1(); }
        __syncthreads();
        if (kt + 2 < 16) issue(kt + 2, (kt + 2) % 3);

        const float* As = smem + (kt % 3) * STAGEFL;
        const float* Bs = As + AFL;

#pragma unroll
        for (int ks = 0; ks < 4; ks++) {
            const int kk = ks * 8;
            float a[4][4];
#pragma unroll
            for (int mf = 0; mf < 4; mf++) {
                const int rr = wm * 64 + mf * 16 + l4;
                const float* p = As + rr * AST + kk + lm4;
                a[mf][0] = tf32r(p[0]);
                a[mf][1] = tf32r(p[8 * AST]);
                a[mf][2] = tf32r(p[4]);
                a[mf][3] = tf32r(p[8 * AST + 4]);
            }
            float bq[4][2];
#pragma unroll
            for (int nf = 0; nf < 4; nf++) {
                const int col = wn * 32 + nf * 8 + l4;
                bq[nf][0] = Bs[(kk + lm4) * BST + col];       // already tf32
                bq[nf][1] = Bs[(kk + lm4 + 4) * BST + col];
            }
#pragma unroll
            for (int mf = 0; mf < 4; mf++)
#pragma unroll
                for (int nf = 0; nf < 4; nf++)
                    mma_tf32(acc[mf][nf], a[mf], bq[nf]);
        }
    }

    // fused epilogue: +h2, tanh, dot Wv chunk -> per-row partial scores
    const float* h2b = h2s + wm * 128;
#pragma unroll
    for (int mf = 0; mf < 4; mf++) {
        float p0 = 0.f, p1 = 0.f;
#pragma unroll
        for (int nf = 0; nf < 4; nf++) {
            const int u = wn * 32 + nf * 8 + 2 * lm4;
            const float h2a = h2b[u], h2c = h2b[u + 1];
            const float wa = wvs[u], wb = wvs[u + 1];
            p0 += tanhf(acc[mf][nf][0] + h2a) * wa + tanhf(acc[mf][nf][1] + h2c) * wb;
            p1 += tanhf(acc[mf][nf][2] + h2a) * wa + tanhf(acc[mf][nf][3] + h2c) * wb;
        }
        p0 += __shfl_xor_sync(0xffffffffu, p0, 1);
        p0 += __shfl_xor_sync(0xffffffffu, p0, 2);
        p1 += __shfl_xor_sync(0xffffffffu, p1, 1);
        p1 += __shfl_xor_sync(0xffffffffu, p1, 2);
        if (lm4 == 0) {
            const int lr = wm * 64 + mf * 16 + l4;
            atomicAdd(&scs[lr], p0);
            atomicAdd(&scs[lr + 8], p1);
        }
    }
    __syncthreads();

    if (tid < 128) {
        const int b = b0 + (tid >> 6), s = tid & 63;
        scores_part[((size_t)b * 4 + uc) * SEQ + s] = scs[tid];
    }
}

// ---------------------------------------------------------------------------
// Kernel B: sum partials -> softmax over seq -> context = sum_s w_s * feat
// ---------------------------------------------------------------------------
__global__ __launch_bounds__(256) void attnB_kernel(
    const float* __restrict__ features,
    const float* __restrict__ sp,
    float* __restrict__ out)
{
    __shared__ float sc[64];
    __shared__ float wts[64];
    const int b = blockIdx.x;
    const int tid = threadIdx.x, lane = tid & 31;

    if (tid < 64) {
        const float* p = sp + (size_t)b * 256 + tid;
        sc[tid] = p[0] + p[64] + p[128] + p[192];
    }
    __syncthreads();

    if (tid < 32) {
        float s0 = sc[lane], s1 = sc[lane + 32];
        float m = fmaxf(s0, s1);
#pragma unroll
        for (int off = 16; off > 0; off >>= 1)
            m = fmaxf(m, __shfl_xor_sync(0xffffffffu, m, off));
        float e0 = __expf(s0 - m), e1 = __expf(s1 - m);
        float sum = e0 + e1;
#pragma unroll
        for (int off = 16; off > 0; off >>= 1)
            sum += __shfl_xor_sync(0xffffffffu, sum, off);
        const float inv = 1.f / sum;
        wts[lane]      = e0 * inv;
        wts[lane + 32] = e1 * inv;
    }
    __syncthreads();

    const int e = tid * 2;
    const float* f = features + (size_t)b * SEQ * EDIM + e;
    float x = 0.f, y = 0.f;
#pragma unroll 8
    for (int s = 0; s < 64; s++) {
        const float2 v = *(const float2*)(f + (size_t)s * EDIM);
        x += wts[s] * v.x;
        y += wts[s] * v.y;
    }
    float2 o; o.x = x; o.y = y;
    *(float2*)(out + (size_t)b * EDIM + e) = o;
}

// ---------------------------------------------------------------------------
// launch
// ---------------------------------------------------------------------------
extern "C" void kernel_launch(void* const* d_in, const int* in_sizes, int n_in,
                              void* d_out, int out_size)
{
    const float* features = (const float*)d_in[0];
    const float* hidden   = (const float*)d_in[1];
    const float* W1       = (const float*)d_in[2];
    const float* b1       = (const float*)d_in[3];
    const float* W2       = (const float*)d_in[4];
    const float* b2       = (const float*)d_in[5];
    const float* Wv       = (const float*)d_in[6];
    // d_in[7] = bv: constant shift, softmax-invariant -> dropped.
    float* out = (float*)d_out;

    float *h2e, *w1tf, *sp;
    cudaGetSymbolAddress((void**)&h2e,  g_h2e);
    cudaGetSymbolAddress((void**)&w1tf, g_w1tf);
    cudaGetSymbolAddress((void**)&sp,   g_sp);

    // K0: W1 -> tf32
    convW1_kernel<<<(EDIM * UDIM / 4) / 256, 256>>>(W1, w1tf);

    // K1: h2e
    {
        dim3 grid(UDIM / 64, BATCH / 64);
        h2_kernel<<<grid, 256>>>(hidden, W2, b1, b2, h2e);
    }

    // KA: big GEMM + tanh/Wv partial scores
    {
        const size_t smem_bytes = SMEMA_FLOATS * sizeof(float);
        cudaFuncSetAttribute(attnA_kernel,
                             cudaFuncAttributeMaxDynamicSharedMemorySize,
                             (int)smem_bytes);
        dim3 grid(4, BATCH / 2);
        attnA_kernel<<<grid, 256, smem_bytes>>>(features, w1tf, Wv, h2e, sp);
    }

    // KB: softmax + context
    attnB_kernel<<<BATCH, 256>>>(features, sp, out);
}